// round 1
// baseline (speedup 1.0000x reference)
#include <cuda_runtime.h>
#include <cuda_bf16.h>

// ---------------------------------------------------------------------------
// Problem constants
//   b=4, n=4096, D=512, H=8, dh=64, M=256 landmarks, l=16, 6 pinv iters,
//   conv k=33, LN eps=1e-5
// ---------------------------------------------------------------------------
#define NB   (4*4096*512)       // 8388608 elems (== 32*4096*64)
#define MM   (32*256*256)       // 2097152
#define MD   (32*256*64)        // 524288

// Scratch (no cudaMalloc allowed)
__device__ float g_xn[NB];
__device__ float g_q[NB];
__device__ float g_k[NB];
__device__ float g_v[NB];
__device__ float g_ql[MD];
__device__ float g_kl[MD];
__device__ float g_a2[MM];
__device__ float g_z0[MM];
__device__ float g_z1[MM];
__device__ float g_t1[MM];
__device__ float g_t2[MM];
__device__ float g_t3[MM];
__device__ float g_w[MD];
__device__ float g_w2[MD];
__device__ float g_attn[NB];    // [bh][n][64]
__device__ float g_attn2[NB];   // [b][n][512]
__device__ float g_red[2];

// ---------------------------------------------------------------------------
// LayerNorm: 16384 rows of 512
// ---------------------------------------------------------------------------
__global__ void ln_kernel(const float* __restrict__ x, const float* __restrict__ w,
                          const float* __restrict__ bb, float* __restrict__ out) {
    int row = blockIdx.x;
    const float* xr = x + (size_t)row * 512;
    float* orow = out + (size_t)row * 512;
    int t = threadIdx.x;                 // 128 threads
    float v[4];
    float s = 0.f;
#pragma unroll
    for (int i = 0; i < 4; i++) { v[i] = xr[t + 128*i]; s += v[i]; }
#pragma unroll
    for (int o = 16; o; o >>= 1) s += __shfl_xor_sync(0xffffffffu, s, o);
    __shared__ float red[4];
    if ((t & 31) == 0) red[t >> 5] = s;
    __syncthreads();
    float mean = (red[0]+red[1]+red[2]+red[3]) * (1.f/512.f);
    float vs = 0.f;
#pragma unroll
    for (int i = 0; i < 4; i++) { float d = v[i]-mean; vs += d*d; }
#pragma unroll
    for (int o = 16; o; o >>= 1) vs += __shfl_xor_sync(0xffffffffu, vs, o);
    __syncthreads();
    if ((t & 31) == 0) red[t >> 5] = vs;
    __syncthreads();
    float var = (red[0]+red[1]+red[2]+red[3]) * (1.f/512.f);
    float rstd = rsqrtf(var + 1e-5f);
#pragma unroll
    for (int i = 0; i < 4; i++) {
        int c = t + 128*i;
        orow[c] = (v[i]-mean)*rstd*w[c] + bb[c];
    }
}

// ---------------------------------------------------------------------------
// QKV GEMM: xn[16384,512] @ Wqkv[512,1536], scattered to q/k/v [bh][n][64],
// q scaled by 1/8. 128x128 tile, BK=8, 8x8 micro.
// ---------------------------------------------------------------------------
__global__ __launch_bounds__(256) void qkv_gemm_kernel(
        const float* __restrict__ Xn, const float* __restrict__ W,
        float* __restrict__ gq, float* __restrict__ gk, float* __restrict__ gv) {
    __shared__ float As[8][132];
    __shared__ float Bs[8][128];
    int t = threadIdx.x;
    int row0 = blockIdx.y * 128, col0 = blockIdx.x * 128;
    int tx = t & 15, ty = t >> 4;
    float acc[8][8];
#pragma unroll
    for (int i=0;i<8;i++)
#pragma unroll
        for (int j=0;j<8;j++) acc[i][j]=0.f;
    int ar = t >> 1, ak = (t & 1) * 4;
    int br = t >> 5, bc = (t & 31) * 4;
    for (int k0 = 0; k0 < 512; k0 += 8) {
        float4 av = *(const float4*)&Xn[(size_t)(row0+ar)*512 + k0 + ak];
        As[ak+0][ar]=av.x; As[ak+1][ar]=av.y; As[ak+2][ar]=av.z; As[ak+3][ar]=av.w;
        *(float4*)&Bs[br][bc] = *(const float4*)&W[(size_t)(k0+br)*1536 + col0 + bc];
        __syncthreads();
#pragma unroll
        for (int k = 0; k < 8; k++) {
            float a[8], b[8];
            *(float4*)&a[0] = *(const float4*)&As[k][ty*8];
            *(float4*)&a[4] = *(const float4*)&As[k][ty*8+4];
            *(float4*)&b[0] = *(const float4*)&Bs[k][tx*8];
            *(float4*)&b[4] = *(const float4*)&Bs[k][tx*8+4];
#pragma unroll
            for (int i=0;i<8;i++)
#pragma unroll
                for (int j=0;j<8;j++) acc[i][j] += a[i]*b[j];
        }
        __syncthreads();
    }
#pragma unroll
    for (int i=0;i<8;i++) {
        int r = row0 + ty*8 + i;
        int b4 = r >> 12, nn = r & 4095;
#pragma unroll
        for (int j=0;j<8;j++) {
            int c = col0 + tx*8 + j;
            int which = c >> 9, cc = c & 511;
            int h = cc >> 6, dh = cc & 63;
            size_t di = ((size_t)(b4*8+h)*4096 + nn)*64 + dh;
            float val = acc[i][j];
            if (which == 0) gq[di] = val * 0.125f;
            else if (which == 1) gk[di] = val;
            else gv[di] = val;
        }
    }
}

// ---------------------------------------------------------------------------
// Output GEMM: attn2[16384,512] @ Wout[512,512] + bout + x -> out
// ---------------------------------------------------------------------------
__global__ __launch_bounds__(256) void out_gemm_kernel(
        const float* __restrict__ A, const float* __restrict__ W,
        const float* __restrict__ bias, const float* __restrict__ x,
        float* __restrict__ out) {
    __shared__ float As[8][132];
    __shared__ float Bs[8][128];
    int t = threadIdx.x;
    int row0 = blockIdx.y * 128, col0 = blockIdx.x * 128;
    int tx = t & 15, ty = t >> 4;
    float acc[8][8];
#pragma unroll
    for (int i=0;i<8;i++)
#pragma unroll
        for (int j=0;j<8;j++) acc[i][j]=0.f;
    int ar = t >> 1, ak = (t & 1) * 4;
    int br = t >> 5, bc = (t & 31) * 4;
    for (int k0 = 0; k0 < 512; k0 += 8) {
        float4 av = *(const float4*)&A[(size_t)(row0+ar)*512 + k0 + ak];
        As[ak+0][ar]=av.x; As[ak+1][ar]=av.y; As[ak+2][ar]=av.z; As[ak+3][ar]=av.w;
        *(float4*)&Bs[br][bc] = *(const float4*)&W[(size_t)(k0+br)*512 + col0 + bc];
        __syncthreads();
#pragma unroll
        for (int k = 0; k < 8; k++) {
            float a[8], b[8];
            *(float4*)&a[0] = *(const float4*)&As[k][ty*8];
            *(float4*)&a[4] = *(const float4*)&As[k][ty*8+4];
            *(float4*)&b[0] = *(const float4*)&Bs[k][tx*8];
            *(float4*)&b[4] = *(const float4*)&Bs[k][tx*8+4];
#pragma unroll
            for (int i=0;i<8;i++)
#pragma unroll
                for (int j=0;j<8;j++) acc[i][j] += a[i]*b[j];
        }
        __syncthreads();
    }
#pragma unroll
    for (int i=0;i<8;i++) {
        int r = row0 + ty*8 + i;
#pragma unroll
        for (int j=0;j<8;j++) {
            int c = col0 + tx*8 + j;
            out[(size_t)r*512 + c] = acc[i][j] + bias[c] + x[(size_t)r*512 + c];
        }
    }
}

// ---------------------------------------------------------------------------
// Landmarks: mean over 16 consecutive rows. src [bh][4096][64] -> dst [bh][256][64]
// ---------------------------------------------------------------------------
__global__ void landmark_kernel(const float* __restrict__ src, float* __restrict__ dst) {
    int idx = blockIdx.x * 256 + threadIdx.x;   // < 524288
    int dh = idx & 63;
    int mi = (idx >> 6) & 255;
    int bh = idx >> 14;
    const float* p = src + ((size_t)bh*4096 + mi*16)*64 + dh;
    float s = 0.f;
#pragma unroll
    for (int j = 0; j < 16; j++) s += p[j*64];
    dst[idx] = s * 0.0625f;
}

// ---------------------------------------------------------------------------
// a2 = softmax(q_l @ k_l^T), rows of 256. 8 rows/block (1 row per warp).
// ---------------------------------------------------------------------------
__global__ __launch_bounds__(256) void a2_kernel(const float* __restrict__ ql,
        const float* __restrict__ kl, float* __restrict__ a2) {
    __shared__ float klt[256][17];
    int bh = blockIdx.y;
    int r = blockIdx.x * 8 + (threadIdx.x >> 5);
    int lane = threadIdx.x & 31;
    const float* qr = ql + ((size_t)bh*256 + r) * 64;
    const float* kb = kl + (size_t)bh*256*64;
    float acc[8];
#pragma unroll
    for (int i=0;i<8;i++) acc[i]=0.f;
    for (int k0 = 0; k0 < 64; k0 += 16) {
        int c = threadIdx.x;
#pragma unroll
        for (int ii=0; ii<4; ii++) {
            float4 kv = *(const float4*)&kb[(size_t)c*64 + k0 + ii*4];
            klt[c][ii*4+0]=kv.x; klt[c][ii*4+1]=kv.y; klt[c][ii*4+2]=kv.z; klt[c][ii*4+3]=kv.w;
        }
        __syncthreads();
#pragma unroll
        for (int kk=0;kk<16;kk++) {
            float qv = qr[k0+kk];
#pragma unroll
            for (int ii=0;ii<8;ii++) acc[ii] += qv * klt[ii*32+lane][kk];
        }
        __syncthreads();
    }
    float m = acc[0];
#pragma unroll
    for (int ii=1;ii<8;ii++) m = fmaxf(m, acc[ii]);
#pragma unroll
    for (int o=16;o;o>>=1) m = fmaxf(m, __shfl_xor_sync(0xffffffffu,m,o));
    float ssum = 0.f;
#pragma unroll
    for (int ii=0;ii<8;ii++){ acc[ii]=__expf(acc[ii]-m); ssum+=acc[ii]; }
#pragma unroll
    for (int o=16;o;o>>=1) ssum += __shfl_xor_sync(0xffffffffu,ssum,o);
    float inv = 1.f/ssum;
    float* orow = a2 + ((size_t)bh*256 + r) * 256;
#pragma unroll
    for (int ii=0;ii<8;ii++) orow[ii*32+lane] = acc[ii]*inv;
}

// ---------------------------------------------------------------------------
// pinv scalar reductions (global over all bh)
// ---------------------------------------------------------------------------
__global__ void red_init_kernel(float* g) { if (threadIdx.x < 2) g[threadIdx.x] = 0.f; }

__global__ void colsum_kernel(const float* __restrict__ a2, float* __restrict__ gred) {
    // max over columns of column-sums -> gred[1]
    int bh = blockIdx.x; int j = threadIdx.x;
    const float* base = a2 + (size_t)bh*65536;
    float s = 0.f;
    for (int i=0;i<256;i++) s += fabsf(base[(size_t)i*256 + j]);
#pragma unroll
    for (int o=16;o;o>>=1) s = fmaxf(s, __shfl_xor_sync(0xffffffffu,s,o));
    __shared__ float red[8];
    if ((j&31)==0) red[j>>5]=s;
    __syncthreads();
    if (j==0) {
        float m = red[0];
#pragma unroll
        for (int u=1;u<8;u++) m = fmaxf(m, red[u]);
        atomicMax((int*)&gred[1], __float_as_int(m));
    }
}

__global__ void rowsum_kernel(const float* __restrict__ a2, float* __restrict__ gred) {
    // max over rows of row-sums -> gred[0]
    int bh = blockIdx.x; int j = threadIdx.x;
    const float* base = a2 + (size_t)bh*65536;
    float s = 0.f;
    for (int i=0;i<256;i++) s += fabsf(base[(size_t)j*256 + i]);
#pragma unroll
    for (int o=16;o;o>>=1) s = fmaxf(s, __shfl_xor_sync(0xffffffffu,s,o));
    __shared__ float red[8];
    if ((j&31)==0) red[j>>5]=s;
    __syncthreads();
    if (j==0) {
        float m = red[0];
#pragma unroll
        for (int u=1;u<8;u++) m = fmaxf(m, red[u]);
        atomicMax((int*)&gred[0], __float_as_int(m));
    }
}

__global__ void zinit_kernel(const float* __restrict__ a2, const float* __restrict__ gred,
                             float* __restrict__ z) {
    int idx = blockIdx.x*256 + threadIdx.x;
    int j = idx & 255, i = (idx>>8) & 255, bh = idx >> 16;
    float inv = 1.f/(gred[0]*gred[1]);
    z[idx] = a2[((size_t)bh*256 + j)*256 + i] * inv;
}

// ---------------------------------------------------------------------------
// Batched GEMM with fused diag/elementwise epilogue:
//   C = cA*A + cAB*(A @ B), A [32][256][256], B/C [32][256][ncols]
// Tile 128x64, BK=16, 8x4 micro. grid (ncols/64, 2, 32)
// ---------------------------------------------------------------------------
__global__ __launch_bounds__(256) void gemm_b_kernel(
        const float* __restrict__ A, const float* __restrict__ B,
        float* __restrict__ C, float cA, float cAB, int ncols) {
    int bh = blockIdx.z;
    int row0 = blockIdx.y * 128;
    int col0 = blockIdx.x * 64;
    const float* Ab = A + (size_t)bh * 65536;
    const float* Bb = B + (size_t)bh * 256 * ncols;
    float* Cb = C + (size_t)bh * 256 * ncols;
    __shared__ float As[16][132];
    __shared__ float Bs[16][64];
    int t = threadIdx.x;
    int tx = t & 15, ty = t >> 4;
    float acc[8][4];
#pragma unroll
    for (int i=0;i<8;i++)
#pragma unroll
        for (int j=0;j<4;j++) acc[i][j]=0.f;
    int alr = t >> 1;
    int alk = (t & 1) * 8;
    int blr = t >> 4;
    int blc = (t & 15) * 4;
    for (int k0 = 0; k0 < 256; k0 += 16) {
#pragma unroll
        for (int ii=0; ii<2; ii++) {
            float4 av = *(const float4*)&Ab[(size_t)(row0+alr)*256 + k0 + alk + ii*4];
            As[alk+ii*4+0][alr]=av.x; As[alk+ii*4+1][alr]=av.y;
            As[alk+ii*4+2][alr]=av.z; As[alk+ii*4+3][alr]=av.w;
        }
        *(float4*)&Bs[blr][blc] = *(const float4*)&Bb[(size_t)(k0+blr)*ncols + col0 + blc];
        __syncthreads();
#pragma unroll
        for (int k=0;k<16;k++) {
            float a[8], b[4];
            *(float4*)&a[0] = *(const float4*)&As[k][ty*8];
            *(float4*)&a[4] = *(const float4*)&As[k][ty*8+4];
            *(float4*)&b[0] = *(const float4*)&Bs[k][tx*4];
#pragma unroll
            for (int i=0;i<8;i++)
#pragma unroll
                for (int j=0;j<4;j++) acc[i][j] += a[i]*b[j];
        }
        __syncthreads();
    }
#pragma unroll
    for (int i=0;i<8;i++) {
        int r = row0 + ty*8 + i;
#pragma unroll
        for (int j=0;j<4;j++) {
            int c = col0 + tx*4 + j;
            float val = cAB * acc[i][j];
            if (cA != 0.f) val += cA * Ab[(size_t)r*256 + c];
            Cb[(size_t)r*ncols + c] = val;
        }
    }
}

// ---------------------------------------------------------------------------
// Flash attention: O = softmax(Q @ K^T) @ V
//   Q [32][nq][64], K/V [32][nk][64], O [32][nq][64]. grid (nq/64, 32), 256 thr
// ---------------------------------------------------------------------------
#define SMEM_FLASH 74240
__global__ __launch_bounds__(256) void flash_kernel(
        const float* __restrict__ Q, const float* __restrict__ K,
        const float* __restrict__ V, float* __restrict__ O, int nq, int nk) {
    extern __shared__ float sm[];
    float (*Qs)[68] = (float(*)[68])sm;
    float (*Ks)[68] = (float(*)[68])(sm + 64*68);
    float (*Ps)[68] = (float(*)[68])(sm + 2*64*68);
    float (*Vs)[68] = (float(*)[68])(sm + 3*64*68);
    float* rowm = sm + 4*64*68;
    float* rowl = rowm + 64;
    float (*red)[16] = (float(*)[16])(rowl + 64);

    int bh = blockIdx.y;
    int q0 = blockIdx.x * 64;
    const float* Qb = Q + ((size_t)bh*nq + q0) * 64;
    const float* Kb = K + (size_t)bh*nk*64;
    const float* Vb = V + (size_t)bh*nk*64;
    float* Ob = O + ((size_t)bh*nq + q0) * 64;

    int t = threadIdx.x;
    int tx = t & 15, ty = t >> 4;
    {
        int r = t >> 2;
        int kb = (t & 3) * 16;
#pragma unroll
        for (int ii=0; ii<4; ii++) {
            float4 qv = *(const float4*)&Qb[(size_t)r*64 + kb + ii*4];
            Qs[kb+ii*4+0][r]=qv.x; Qs[kb+ii*4+1][r]=qv.y;
            Qs[kb+ii*4+2][r]=qv.z; Qs[kb+ii*4+3][r]=qv.w;
        }
    }
    if (t < 64) { rowm[t] = -1e30f; rowl[t] = 0.f; }
    float acc[4][4];
#pragma unroll
    for (int i=0;i<4;i++)
#pragma unroll
        for (int j=0;j<4;j++) acc[i][j]=0.f;
    __syncthreads();

    for (int c0 = 0; c0 < nk; c0 += 64) {
        {
            int r = t >> 2;
            int kb = (t & 3) * 16;
#pragma unroll
            for (int ii=0; ii<4; ii++) {
                float4 kv = *(const float4*)&Kb[(size_t)(c0+r)*64 + kb + ii*4];
                Ks[kb+ii*4+0][r]=kv.x; Ks[kb+ii*4+1][r]=kv.y;
                Ks[kb+ii*4+2][r]=kv.z; Ks[kb+ii*4+3][r]=kv.w;
                float4 vv = *(const float4*)&Vb[(size_t)(c0+r)*64 + kb + ii*4];
                *(float4*)&Vs[r][kb+ii*4] = vv;
            }
        }
        __syncthreads();
        float s[4][4];
#pragma unroll
        for (int i=0;i<4;i++)
#pragma unroll
            for(int j=0;j<4;j++) s[i][j]=0.f;
#pragma unroll 8
        for (int k=0;k<64;k++) {
            float a[4], b[4];
            *(float4*)&a[0] = *(const float4*)&Qs[k][ty*4];
            *(float4*)&b[0] = *(const float4*)&Ks[k][tx*4];
#pragma unroll
            for (int i=0;i<4;i++)
#pragma unroll
                for (int j=0;j<4;j++) s[i][j] += a[i]*b[j];
        }
#pragma unroll
        for (int i=0;i<4;i++) {
            float pm = fmaxf(fmaxf(s[i][0],s[i][1]), fmaxf(s[i][2],s[i][3]));
            red[ty*4+i][tx] = pm;
        }
        __syncthreads();
        float mnew[4], scale[4];
#pragma unroll
        for (int i=0;i<4;i++) {
            int r = ty*4+i;
            float m = red[r][0];
#pragma unroll
            for (int jj=1;jj<16;jj++) m = fmaxf(m, red[r][jj]);
            float mo = rowm[r];
            mnew[i] = fmaxf(mo, m);
            scale[i] = __expf(mo - mnew[i]);
        }
        __syncthreads();
#pragma unroll
        for (int i=0;i<4;i++) {
            float ps = 0.f;
#pragma unroll
            for (int j=0;j<4;j++) {
                float p = __expf(s[i][j] - mnew[i]);
                Ps[tx*4+j][ty*4+i] = p;
                ps += p;
                acc[i][j] *= scale[i];
            }
            red[ty*4+i][tx] = ps;
            if (tx == 0) rowm[ty*4+i] = mnew[i];
        }
        __syncthreads();
        if (tx == 0) {
#pragma unroll
            for (int i=0;i<4;i++) {
                int r = ty*4+i;
                float cs = 0.f;
#pragma unroll
                for (int jj=0;jj<16;jj++) cs += red[r][jj];
                rowl[r] = rowl[r]*scale[i] + cs;
            }
        }
#pragma unroll 8
        for (int c=0;c<64;c++) {
            float a[4], b[4];
            *(float4*)&a[0] = *(const float4*)&Ps[c][ty*4];
            *(float4*)&b[0] = *(const float4*)&Vs[c][tx*4];
#pragma unroll
            for (int i=0;i<4;i++)
#pragma unroll
                for (int j=0;j<4;j++) acc[i][j] += a[i]*b[j];
        }
        __syncthreads();
    }
#pragma unroll
    for (int i=0;i<4;i++) {
        int r = ty*4+i;
        float inv = 1.f / rowl[r];
        float4 o;
        o.x = acc[i][0]*inv; o.y = acc[i][1]*inv;
        o.z = acc[i][2]*inv; o.w = acc[i][3]*inv;
        *(float4*)&Ob[(size_t)r*64 + tx*4] = o;
    }
}

// ---------------------------------------------------------------------------
// Depthwise seq-conv residual + layout transform:
//   attn2[b][n][h*64+dh] = attn[bh][n][dh] + sum_s w[h][s]*v[bh][n-16+s][dh]
// ---------------------------------------------------------------------------
__global__ __launch_bounds__(256) void conv_kernel(
        const float* __restrict__ attn, const float* __restrict__ v,
        const float* __restrict__ cw, float* __restrict__ attn2) {
    __shared__ float vt[96][64];
    __shared__ float wk[33];
    int bh = blockIdx.y; int h = bh & 7; int b4 = bh >> 3;
    int row0 = blockIdx.x * 64;
    int t = threadIdx.x;
    if (t < 33) wk[t] = cw[h*33 + t];
    const float* vb = v + (size_t)bh*4096*64;
#pragma unroll
    for (int i=0;i<6;i++){
        int f = t + i*256;        // 0..1535 -> 96 rows x 16 float4
        int r = f >> 4;
        int c4 = (f & 15) * 4;
        int gr = row0 - 16 + r;
        float4 val = make_float4(0.f,0.f,0.f,0.f);
        if (gr >= 0 && gr < 4096) val = *(const float4*)&vb[(size_t)gr*64 + c4];
        *(float4*)&vt[r][c4] = val;
    }
    __syncthreads();
    int dh = t & 63;
    int rr = t >> 6;
#pragma unroll
    for (int q=0;q<16;q++){
        int lr = rr + q*4;
        float acc = attn[((size_t)bh*4096 + row0 + lr)*64 + dh];
#pragma unroll
        for (int s=0;s<33;s++) acc += wk[s]*vt[lr+s][dh];
        attn2[((size_t)b4*4096 + row0 + lr)*512 + h*64 + dh] = acc;
    }
}

// ---------------------------------------------------------------------------
// Host orchestration
// ---------------------------------------------------------------------------
extern "C" void kernel_launch(void* const* d_in, const int* in_sizes, int n_in,
                              void* d_out, int out_size) {
    const float* x      = (const float*)d_in[0];
    const float* norm_w = (const float*)d_in[1];
    const float* norm_b = (const float*)d_in[2];
    const float* Wqkv   = (const float*)d_in[3];
    const float* Wout   = (const float*)d_in[4];
    const float* bout   = (const float*)d_in[5];
    const float* conv_w = (const float*)d_in[6];
    float* out = (float*)d_out;

    float *xn,*q,*k,*v,*ql,*kl,*a2,*z0,*z1,*t1,*t2,*t3,*w,*w2,*attn,*attn2,*red;
    cudaGetSymbolAddress((void**)&xn,   g_xn);
    cudaGetSymbolAddress((void**)&q,    g_q);
    cudaGetSymbolAddress((void**)&k,    g_k);
    cudaGetSymbolAddress((void**)&v,    g_v);
    cudaGetSymbolAddress((void**)&ql,   g_ql);
    cudaGetSymbolAddress((void**)&kl,   g_kl);
    cudaGetSymbolAddress((void**)&a2,   g_a2);
    cudaGetSymbolAddress((void**)&z0,   g_z0);
    cudaGetSymbolAddress((void**)&z1,   g_z1);
    cudaGetSymbolAddress((void**)&t1,   g_t1);
    cudaGetSymbolAddress((void**)&t2,   g_t2);
    cudaGetSymbolAddress((void**)&t3,   g_t3);
    cudaGetSymbolAddress((void**)&w,    g_w);
    cudaGetSymbolAddress((void**)&w2,   g_w2);
    cudaGetSymbolAddress((void**)&attn, g_attn);
    cudaGetSymbolAddress((void**)&attn2,g_attn2);
    cudaGetSymbolAddress((void**)&red,  g_red);

    cudaFuncSetAttribute(flash_kernel, cudaFuncAttributeMaxDynamicSharedMemorySize, SMEM_FLASH);

    // 1. LayerNorm
    ln_kernel<<<16384, 128>>>(x, norm_w, norm_b, xn);
    // 2. QKV projection (q scaled)
    qkv_gemm_kernel<<<dim3(12,128), 256>>>(xn, Wqkv, q, k, v);
    // 3. landmarks
    landmark_kernel<<<2048, 256>>>(q, ql);
    landmark_kernel<<<2048, 256>>>(k, kl);
    // 4. a2 = softmax(q_l k_l^T)
    a2_kernel<<<dim3(32,32), 256>>>(ql, kl, a2);
    // 5. pinv init scalars + z0 = a2^T/(col*row)
    red_init_kernel<<<1, 32>>>(red);
    colsum_kernel<<<32, 256>>>(a2, red);
    rowsum_kernel<<<32, 256>>>(a2, red);
    zinit_kernel<<<8192, 256>>>(a2, red, z0);
    // 6. w = softmax(q_l k^T) @ v   (flash, 256 queries x 4096 keys)
    flash_kernel<<<dim3(4,32), 256, SMEM_FLASH>>>(ql, k, v, w, 256, 4096);
    // 7. Newton-Schulz pinv: 6 iterations, epilogues fused into GEMMs
    float* zin = z0; float* zout = z1;
    for (int it = 0; it < 6; it++) {
        gemm_b_kernel<<<dim3(4,2,32), 256>>>(a2, zin, t1, 0.f,   1.f,    256); // az
        gemm_b_kernel<<<dim3(4,2,32), 256>>>(t1, t1, t2, 7.f,   -1.f,    256); // az(7I-az)
        gemm_b_kernel<<<dim3(4,2,32), 256>>>(t1, t2, t3, 15.f,  -1.f,    256); // az(15I-u2)
        gemm_b_kernel<<<dim3(4,2,32), 256>>>(zin, t3, zout, 3.25f, -0.25f, 256); // z'
        float* tmp = zin; zin = zout; zout = tmp;
    }
    // 8. w2 = pinv(a2) @ w     [m,m]@[m,64]
    gemm_b_kernel<<<dim3(1,2,32), 256>>>(zin, w, w2, 0.f, 1.f, 64);
    // 9. attn = softmax(q k_l^T) @ w2   (flash, 4096 queries x 256 keys)
    flash_kernel<<<dim3(64,32), 256, SMEM_FLASH>>>(q, kl, w2, attn, 4096, 256);
    // 10. conv residual + [b][n][D] layout
    conv_kernel<<<dim3(64,32), 256>>>(attn, v, conv_w, attn2);
    // 11. output projection + bias + input residual
    out_gemm_kernel<<<dim3(4,128), 256>>>(attn2, Wout, bout, x, out);
}

// round 3
// speedup vs baseline: 1.6457x; 1.6457x over previous
#include <cuda_runtime.h>
#include <cuda_bf16.h>
#include <cstdint>

// ---------------------------------------------------------------------------
// Problem constants: b=4, n=4096, D=512, H=8, dh=64, M=256, l=16, 6 iters,
// conv k=33, eps=1e-5
// ---------------------------------------------------------------------------
#define NB   (4*4096*512)
#define MM   (32*256*256)
#define MD   (32*256*64)

__device__ float g_xn[NB];
__device__ float g_q[NB];
__device__ float g_k[NB];
__device__ float g_v[NB];
__device__ float g_ql[MD];
__device__ float g_kl[MD];
__device__ float g_a2[MM];
__device__ float g_z0[MM];
__device__ float g_z1[MM];
__device__ float g_t1[MM];
__device__ float g_t2[MM];
__device__ float g_t3[MM];
__device__ float g_w[MD];
__device__ float g_w2[MD];
__device__ float g_attn[NB];
__device__ float g_attn2[NB];
__device__ float g_red[2];

__device__ __forceinline__ float f2tf(float x) {
    uint32_t u;
    asm("cvt.rna.tf32.f32 %0, %1;" : "=r"(u) : "f"(x));
    return __uint_as_float(u);
}

// ---------------------------------------------------------------------------
// LayerNorm
// ---------------------------------------------------------------------------
__global__ void ln_kernel(const float* __restrict__ x, const float* __restrict__ w,
                          const float* __restrict__ bb, float* __restrict__ out) {
    int row = blockIdx.x;
    const float* xr = x + (size_t)row * 512;
    float* orow = out + (size_t)row * 512;
    int t = threadIdx.x;
    float v[4];
    float s = 0.f;
#pragma unroll
    for (int i = 0; i < 4; i++) { v[i] = xr[t + 128*i]; s += v[i]; }
#pragma unroll
    for (int o = 16; o; o >>= 1) s += __shfl_xor_sync(0xffffffffu, s, o);
    __shared__ float red[4];
    if ((t & 31) == 0) red[t >> 5] = s;
    __syncthreads();
    float mean = (red[0]+red[1]+red[2]+red[3]) * (1.f/512.f);
    float vs = 0.f;
#pragma unroll
    for (int i = 0; i < 4; i++) { float d = v[i]-mean; vs += d*d; }
#pragma unroll
    for (int o = 16; o; o >>= 1) vs += __shfl_xor_sync(0xffffffffu, vs, o);
    __syncthreads();
    if ((t & 31) == 0) red[t >> 5] = vs;
    __syncthreads();
    float var = (red[0]+red[1]+red[2]+red[3]) * (1.f/512.f);
    float rstd = rsqrtf(var + 1e-5f);
#pragma unroll
    for (int i = 0; i < 4; i++) {
        int c = t + 128*i;
        orow[c] = (v[i]-mean)*rstd*w[c] + bb[c];
    }
}

// ---------------------------------------------------------------------------
// TF32 tensor-core GEMM. Block 128x128, BK=16, 256 thr (8 warps, warp 64x32).
// A row-major [M][LDA], B row-major [K][LDB].
// PTX m16n8k8 tf32 fragment layout (g=lane>>2, t4=lane&3):
//   A: a0=(g,t4) a1=(g+8,t4) a2=(g,t4+4) a3=(g+8,t4+4)
//   B: b0=(k=t4,n=g) b1=(k=t4+4,n=g)
//   C: c0/c1=(g,2t4|2t4+1) c2/c3=(g+8,...)
// EPI 0: QKV scatter (C0=q scaled 0.125, C1=k, C2=v)
// EPI 1: C0[r*512+c] = acc + e0[c] + e1[r*512+c]
// EPI 2: batched (z=blockIdx.z, stride 65536): C0 = cA*A + cAB*(A@B)
// ---------------------------------------------------------------------------
template<int EPI, int LDA, int LDB, int KD>
__global__ __launch_bounds__(256, 2) void mma_gemm(
        const float* __restrict__ A, const float* __restrict__ B,
        float* __restrict__ C0, float* __restrict__ C1, float* __restrict__ C2,
        const float* __restrict__ e0, const float* __restrict__ e1,
        float cA, float cAB) {
    __shared__ float Asm[2][128*20];
    __shared__ float Bsm[2][16*136];
    int tid = threadIdx.x;
    int lane = tid & 31, wid = tid >> 5;
    int wm = wid & 1, wn = wid >> 1;
    int g = lane >> 2, t4 = lane & 3;
    int row0 = blockIdx.y * 128, col0 = blockIdx.x * 128;
    const float* Ag = A;
    const float* Bg = B;
    if (EPI == 2) {
        Ag += (size_t)blockIdx.z * 65536;
        Bg += (size_t)blockIdx.z * 65536;
    }
    int arow = tid >> 1, akq = (tid & 1) * 8;
    int bkr = tid >> 4, bnc = (tid & 15) * 8;

    // stage iteration 0
    {
        const float* ap = Ag + (size_t)(row0 + arow) * LDA + akq;
        float4 a0 = *(const float4*)ap;
        float4 a1 = *(const float4*)(ap + 4);
        float* as = &Asm[0][arow*20 + akq];
        as[0]=f2tf(a0.x); as[1]=f2tf(a0.y); as[2]=f2tf(a0.z); as[3]=f2tf(a0.w);
        as[4]=f2tf(a1.x); as[5]=f2tf(a1.y); as[6]=f2tf(a1.z); as[7]=f2tf(a1.w);
        const float* bp = Bg + (size_t)bkr * LDB + col0 + bnc;
        float4 b0 = *(const float4*)bp;
        float4 b1 = *(const float4*)(bp + 4);
        float* bs = &Bsm[0][bkr*136 + bnc];
        bs[0]=f2tf(b0.x); bs[1]=f2tf(b0.y); bs[2]=f2tf(b0.z); bs[3]=f2tf(b0.w);
        bs[4]=f2tf(b1.x); bs[5]=f2tf(b1.y); bs[6]=f2tf(b1.z); bs[7]=f2tf(b1.w);
    }
    __syncthreads();

    float c[4][4][4];
#pragma unroll
    for (int i=0;i<4;i++)
#pragma unroll
        for (int j=0;j<4;j++)
#pragma unroll
            for (int h=0;h<4;h++) c[i][j][h]=0.f;

    const int NIT = KD / 16;
    for (int it = 0; it < NIT; it++) {
        int buf = it & 1;
        float4 pa0, pa1, pb0, pb1;
        if (it + 1 < NIT) {
            int k0 = (it + 1) * 16;
            const float* ap = Ag + (size_t)(row0 + arow) * LDA + k0 + akq;
            pa0 = *(const float4*)ap;
            pa1 = *(const float4*)(ap + 4);
            const float* bp = Bg + (size_t)(k0 + bkr) * LDB + col0 + bnc;
            pb0 = *(const float4*)bp;
            pb1 = *(const float4*)(bp + 4);
        }
#pragma unroll
        for (int ks = 0; ks < 16; ks += 8) {
            uint32_t af[4][4], bf[4][2];
#pragma unroll
            for (int i = 0; i < 4; i++) {
                int r0i = (wm*64 + i*16 + g) * 20 + ks + t4;
                int r1i = r0i + 8*20;
                af[i][0] = __float_as_uint(Asm[buf][r0i]);
                af[i][1] = __float_as_uint(Asm[buf][r1i]);
                af[i][2] = __float_as_uint(Asm[buf][r0i + 4]);
                af[i][3] = __float_as_uint(Asm[buf][r1i + 4]);
            }
#pragma unroll
            for (int j = 0; j < 4; j++) {
                int nc2 = wn*32 + j*8 + g;
                bf[j][0] = __float_as_uint(Bsm[buf][(ks + t4)*136 + nc2]);
                bf[j][1] = __float_as_uint(Bsm[buf][(ks + t4 + 4)*136 + nc2]);
            }
#pragma unroll
            for (int i = 0; i < 4; i++)
#pragma unroll
                for (int j = 0; j < 4; j++) {
                    asm volatile(
                        "mma.sync.aligned.m16n8k8.row.col.f32.tf32.tf32.f32 "
                        "{%0,%1,%2,%3}, {%4,%5,%6,%7}, {%8,%9}, {%0,%1,%2,%3};\n"
                        : "+f"(c[i][j][0]), "+f"(c[i][j][1]),
                          "+f"(c[i][j][2]), "+f"(c[i][j][3])
                        : "r"(af[i][0]), "r"(af[i][1]), "r"(af[i][2]), "r"(af[i][3]),
                          "r"(bf[j][0]), "r"(bf[j][1]));
                }
        }
        if (it + 1 < NIT) {
            int nb = buf ^ 1;
            float* as = &Asm[nb][arow*20 + akq];
            as[0]=f2tf(pa0.x); as[1]=f2tf(pa0.y); as[2]=f2tf(pa0.z); as[3]=f2tf(pa0.w);
            as[4]=f2tf(pa1.x); as[5]=f2tf(pa1.y); as[6]=f2tf(pa1.z); as[7]=f2tf(pa1.w);
            float* bs = &Bsm[nb][bkr*136 + bnc];
            bs[0]=f2tf(pb0.x); bs[1]=f2tf(pb0.y); bs[2]=f2tf(pb0.z); bs[3]=f2tf(pb0.w);
            bs[4]=f2tf(pb1.x); bs[5]=f2tf(pb1.y); bs[6]=f2tf(pb1.z); bs[7]=f2tf(pb1.w);
        }
        __syncthreads();
    }

    // epilogue
#pragma unroll
    for (int i = 0; i < 4; i++) {
#pragma unroll
        for (int j = 0; j < 4; j++) {
#pragma unroll
            for (int h = 0; h < 2; h++) {
                int r = row0 + wm*64 + i*16 + g + h*8;
                int cc = col0 + wn*32 + j*8 + 2*t4;
                float v0 = c[i][j][h*2+0], v1 = c[i][j][h*2+1];
                if (EPI == 0) {
                    int b4 = r >> 12, nn = r & 4095;
                    int which = cc >> 9, cs = cc & 511;
                    int hh = cs >> 6, dh = cs & 63;
                    size_t di = ((size_t)(b4*8+hh)*4096 + nn)*64 + dh;
                    if (which == 0) {
                        *(float2*)&C0[di] = make_float2(v0*0.125f, v1*0.125f);
                    } else if (which == 1) {
                        *(float2*)&C1[di] = make_float2(v0, v1);
                    } else {
                        *(float2*)&C2[di] = make_float2(v0, v1);
                    }
                } else if (EPI == 1) {
                    size_t di = (size_t)r*512 + cc;
                    float2 bias = *(const float2*)&e0[cc];
                    float2 xr = *(const float2*)&e1[di];
                    *(float2*)&C0[di] = make_float2(v0+bias.x+xr.x, v1+bias.y+xr.y);
                } else {
                    float2 ae = *(const float2*)&Ag[(size_t)r*256 + cc];
                    size_t di = (size_t)blockIdx.z*65536 + (size_t)r*256 + cc;
                    *(float2*)&C0[di] = make_float2(cA*ae.x + cAB*v0,
                                                    cA*ae.y + cAB*v1);
                }
            }
        }
    }
}

// ---------------------------------------------------------------------------
// Landmarks
// ---------------------------------------------------------------------------
__global__ void landmark_kernel(const float* __restrict__ src, float* __restrict__ dst) {
    int idx = blockIdx.x * 256 + threadIdx.x;
    int dh = idx & 63;
    int mi = (idx >> 6) & 255;
    int bh = idx >> 14;
    const float* p = src + ((size_t)bh*4096 + mi*16)*64 + dh;
    float s = 0.f;
#pragma unroll
    for (int j = 0; j < 16; j++) s += p[j*64];
    dst[idx] = s * 0.0625f;
}

// ---------------------------------------------------------------------------
// a2 = softmax(q_l @ k_l^T)
// ---------------------------------------------------------------------------
__global__ __launch_bounds__(256) void a2_kernel(const float* __restrict__ ql,
        const float* __restrict__ kl, float* __restrict__ a2) {
    __shared__ float klt[256][17];
    int bh = blockIdx.y;
    int r = blockIdx.x * 8 + (threadIdx.x >> 5);
    int lane = threadIdx.x & 31;
    const float* qr = ql + ((size_t)bh*256 + r) * 64;
    const float* kb = kl + (size_t)bh*256*64;
    float acc[8];
#pragma unroll
    for (int i=0;i<8;i++) acc[i]=0.f;
    for (int k0 = 0; k0 < 64; k0 += 16) {
        int c = threadIdx.x;
#pragma unroll
        for (int ii=0; ii<4; ii++) {
            float4 kv = *(const float4*)&kb[(size_t)c*64 + k0 + ii*4];
            klt[c][ii*4+0]=kv.x; klt[c][ii*4+1]=kv.y; klt[c][ii*4+2]=kv.z; klt[c][ii*4+3]=kv.w;
        }
        __syncthreads();
#pragma unroll
        for (int kk=0;kk<16;kk++) {
            float qv = qr[k0+kk];
#pragma unroll
            for (int ii=0;ii<8;ii++) acc[ii] += qv * klt[ii*32+lane][kk];
        }
        __syncthreads();
    }
    float m = acc[0];
#pragma unroll
    for (int ii=1;ii<8;ii++) m = fmaxf(m, acc[ii]);
#pragma unroll
    for (int o=16;o;o>>=1) m = fmaxf(m, __shfl_xor_sync(0xffffffffu,m,o));
    float ssum = 0.f;
#pragma unroll
    for (int ii=0;ii<8;ii++){ acc[ii]=__expf(acc[ii]-m); ssum+=acc[ii]; }
#pragma unroll
    for (int o=16;o;o>>=1) ssum += __shfl_xor_sync(0xffffffffu,ssum,o);
    float inv = 1.f/ssum;
    float* orow = a2 + ((size_t)bh*256 + r) * 256;
#pragma unroll
    for (int ii=0;ii<8;ii++) orow[ii*32+lane] = acc[ii]*inv;
}

// ---------------------------------------------------------------------------
// pinv scalar reductions
// ---------------------------------------------------------------------------
__global__ void red_init_kernel(float* g) { if (threadIdx.x < 2) g[threadIdx.x] = 0.f; }

__global__ void colsum_kernel(const float* __restrict__ a2, float* __restrict__ gred) {
    int bh = blockIdx.x; int j = threadIdx.x;
    const float* base = a2 + (size_t)bh*65536;
    float s = 0.f;
    for (int i=0;i<256;i++) s += fabsf(base[(size_t)i*256 + j]);
#pragma unroll
    for (int o=16;o;o>>=1) s = fmaxf(s, __shfl_xor_sync(0xffffffffu,s,o));
    __shared__ float red[8];
    if ((j&31)==0) red[j>>5]=s;
    __syncthreads();
    if (j==0) {
        float m = red[0];
#pragma unroll
        for (int u=1;u<8;u++) m = fmaxf(m, red[u]);
        atomicMax((int*)&gred[1], __float_as_int(m));
    }
}

__global__ void rowsum_kernel(const float* __restrict__ a2, float* __restrict__ gred) {
    int bh = blockIdx.x; int j = threadIdx.x;
    const float* base = a2 + (size_t)bh*65536;
    float s = 0.f;
    for (int i=0;i<256;i++) s += fabsf(base[(size_t)j*256 + i]);
#pragma unroll
    for (int o=16;o;o>>=1) s = fmaxf(s, __shfl_xor_sync(0xffffffffu,s,o));
    __shared__ float red[8];
    if ((j&31)==0) red[j>>5]=s;
    __syncthreads();
    if (j==0) {
        float m = red[0];
#pragma unroll
        for (int u=1;u<8;u++) m = fmaxf(m, red[u]);
        atomicMax((int*)&gred[0], __float_as_int(m));
    }
}

__global__ void zinit_kernel(const float* __restrict__ a2, const float* __restrict__ gred,
                             float* __restrict__ z) {
    int idx = blockIdx.x*256 + threadIdx.x;
    int j = idx & 255, i = (idx>>8) & 255, bh = idx >> 16;
    float inv = 1.f/(gred[0]*gred[1]);
    z[idx] = a2[((size_t)bh*256 + j)*256 + i] * inv;
}

// ---------------------------------------------------------------------------
// fp32 batched GEMM (kept only for the tiny w2 = pinv @ w, ncols=64)
// ---------------------------------------------------------------------------
__global__ __launch_bounds__(256) void gemm_b_kernel(
        const float* __restrict__ A, const float* __restrict__ B,
        float* __restrict__ C, float cA, float cAB, int ncols) {
    int bh = blockIdx.z;
    int row0 = blockIdx.y * 128;
    int col0 = blockIdx.x * 64;
    const float* Ab = A + (size_t)bh * 65536;
    const float* Bb = B + (size_t)bh * 256 * ncols;
    float* Cb = C + (size_t)bh * 256 * ncols;
    __shared__ float As[16][132];
    __shared__ float Bs[16][64];
    int t = threadIdx.x;
    int tx = t & 15, ty = t >> 4;
    float acc[8][4];
#pragma unroll
    for (int i=0;i<8;i++)
#pragma unroll
        for (int j=0;j<4;j++) acc[i][j]=0.f;
    int alr = t >> 1;
    int alk = (t & 1) * 8;
    int blr = t >> 4;
    int blc = (t & 15) * 4;
    for (int k0 = 0; k0 < 256; k0 += 16) {
#pragma unroll
        for (int ii=0; ii<2; ii++) {
            float4 av = *(const float4*)&Ab[(size_t)(row0+alr)*256 + k0 + alk + ii*4];
            As[alk+ii*4+0][alr]=av.x; As[alk+ii*4+1][alr]=av.y;
            As[alk+ii*4+2][alr]=av.z; As[alk+ii*4+3][alr]=av.w;
        }
        *(float4*)&Bs[blr][blc] = *(const float4*)&Bb[(size_t)(k0+blr)*ncols + col0 + blc];
        __syncthreads();
#pragma unroll
        for (int k=0;k<16;k++) {
            float a[8], b[4];
            *(float4*)&a[0] = *(const float4*)&As[k][ty*8];
            *(float4*)&a[4] = *(const float4*)&As[k][ty*8+4];
            *(float4*)&b[0] = *(const float4*)&Bs[k][tx*4];
#pragma unroll
            for (int i=0;i<8;i++)
#pragma unroll
                for (int j=0;j<4;j++) acc[i][j] += a[i]*b[j];
        }
        __syncthreads();
    }
#pragma unroll
    for (int i=0;i<8;i++) {
        int r = row0 + ty*8 + i;
#pragma unroll
        for (int j=0;j<4;j++) {
            int c = col0 + tx*4 + j;
            float val = cAB * acc[i][j];
            if (cA != 0.f) val += cA * Ab[(size_t)r*256 + c];
            Cb[(size_t)r*ncols + c] = val;
        }
    }
}

// ---------------------------------------------------------------------------
// Flash attention: O = softmax(Q @ K^T) @ V
// ---------------------------------------------------------------------------
#define SMEM_FLASH 74240
__global__ __launch_bounds__(256) void flash_kernel(
        const float* __restrict__ Q, const float* __restrict__ K,
        const float* __restrict__ V, float* __restrict__ O, int nq, int nk) {
    extern __shared__ float sm[];
    float (*Qs)[68] = (float(*)[68])sm;
    float (*Ks)[68] = (float(*)[68])(sm + 64*68);
    float (*Ps)[68] = (float(*)[68])(sm + 2*64*68);
    float (*Vs)[68] = (float(*)[68])(sm + 3*64*68);
    float* rowm = sm + 4*64*68;
    float* rowl = rowm + 64;
    float (*red)[16] = (float(*)[16])(rowl + 64);

    int bh = blockIdx.y;
    int q0 = blockIdx.x * 64;
    const float* Qb = Q + ((size_t)bh*nq + q0) * 64;
    const float* Kb = K + (size_t)bh*nk*64;
    const float* Vb = V + (size_t)bh*nk*64;
    float* Ob = O + ((size_t)bh*nq + q0) * 64;

    int t = threadIdx.x;
    int tx = t & 15, ty = t >> 4;
    {
        int r = t >> 2;
        int kb = (t & 3) * 16;
#pragma unroll
        for (int ii=0; ii<4; ii++) {
            float4 qv = *(const float4*)&Qb[(size_t)r*64 + kb + ii*4];
            Qs[kb+ii*4+0][r]=qv.x; Qs[kb+ii*4+1][r]=qv.y;
            Qs[kb+ii*4+2][r]=qv.z; Qs[kb+ii*4+3][r]=qv.w;
        }
    }
    if (t < 64) { rowm[t] = -1e30f; rowl[t] = 0.f; }
    float acc[4][4];
#pragma unroll
    for (int i=0;i<4;i++)
#pragma unroll
        for (int j=0;j<4;j++) acc[i][j]=0.f;
    __syncthreads();

    for (int c0 = 0; c0 < nk; c0 += 64) {
        {
            int r = t >> 2;
            int kb = (t & 3) * 16;
#pragma unroll
            for (int ii=0; ii<4; ii++) {
                float4 kv = *(const float4*)&Kb[(size_t)(c0+r)*64 + kb + ii*4];
                Ks[kb+ii*4+0][r]=kv.x; Ks[kb+ii*4+1][r]=kv.y;
                Ks[kb+ii*4+2][r]=kv.z; Ks[kb+ii*4+3][r]=kv.w;
                float4 vv = *(const float4*)&Vb[(size_t)(c0+r)*64 + kb + ii*4];
                *(float4*)&Vs[r][kb+ii*4] = vv;
            }
        }
        __syncthreads();
        float s[4][4];
#pragma unroll
        for (int i=0;i<4;i++)
#pragma unroll
            for(int j=0;j<4;j++) s[i][j]=0.f;
#pragma unroll 8
        for (int k=0;k<64;k++) {
            float a[4], b[4];
            *(float4*)&a[0] = *(const float4*)&Qs[k][ty*4];
            *(float4*)&b[0] = *(const float4*)&Ks[k][tx*4];
#pragma unroll
            for (int i=0;i<4;i++)
#pragma unroll
                for (int j=0;j<4;j++) s[i][j] += a[i]*b[j];
        }
#pragma unroll
        for (int i=0;i<4;i++) {
            float pm = fmaxf(fmaxf(s[i][0],s[i][1]), fmaxf(s[i][2],s[i][3]));
            red[ty*4+i][tx] = pm;
        }
        __syncthreads();
        float mnew[4], scale[4];
#pragma unroll
        for (int i=0;i<4;i++) {
            int r = ty*4+i;
            float m = red[r][0];
#pragma unroll
            for (int jj=1;jj<16;jj++) m = fmaxf(m, red[r][jj]);
            float mo = rowm[r];
            mnew[i] = fmaxf(mo, m);
            scale[i] = __expf(mo - mnew[i]);
        }
        __syncthreads();
#pragma unroll
        for (int i=0;i<4;i++) {
            float ps = 0.f;
#pragma unroll
            for (int j=0;j<4;j++) {
                float p = __expf(s[i][j] - mnew[i]);
                Ps[tx*4+j][ty*4+i] = p;
                ps += p;
                acc[i][j] *= scale[i];
            }
            red[ty*4+i][tx] = ps;
            if (tx == 0) rowm[ty*4+i] = mnew[i];
        }
        __syncthreads();
        if (tx == 0) {
#pragma unroll
            for (int i=0;i<4;i++) {
                int r = ty*4+i;
                float cs = 0.f;
#pragma unroll
                for (int jj=0;jj<16;jj++) cs += red[r][jj];
                rowl[r] = rowl[r]*scale[i] + cs;
            }
        }
#pragma unroll 8
        for (int c=0;c<64;c++) {
            float a[4], b[4];
            *(float4*)&a[0] = *(const float4*)&Ps[c][ty*4];
            *(float4*)&b[0] = *(const float4*)&Vs[c][tx*4];
#pragma unroll
            for (int i=0;i<4;i++)
#pragma unroll
                for (int j=0;j<4;j++) acc[i][j] += a[i]*b[j];
        }
        __syncthreads();
    }
#pragma unroll
    for (int i=0;i<4;i++) {
        int r = ty*4+i;
        float inv = 1.f / rowl[r];
        float4 o;
        o.x = acc[i][0]*inv; o.y = acc[i][1]*inv;
        o.z = acc[i][2]*inv; o.w = acc[i][3]*inv;
        *(float4*)&Ob[(size_t)r*64 + tx*4] = o;
    }
}

// ---------------------------------------------------------------------------
// Depthwise seq-conv residual + layout transform
// ---------------------------------------------------------------------------
__global__ __launch_bounds__(256) void conv_kernel(
        const float* __restrict__ attn, const float* __restrict__ v,
        const float* __restrict__ cw, float* __restrict__ attn2) {
    __shared__ float vt[96][64];
    __shared__ float wk[33];
    int bh = blockIdx.y; int h = bh & 7; int b4 = bh >> 3;
    int row0 = blockIdx.x * 64;
    int t = threadIdx.x;
    if (t < 33) wk[t] = cw[h*33 + t];
    const float* vb = v + (size_t)bh*4096*64;
#pragma unroll
    for (int i=0;i<6;i++){
        int f = t + i*256;
        int r = f >> 4;
        int c4 = (f & 15) * 4;
        int gr = row0 - 16 + r;
        float4 val = make_float4(0.f,0.f,0.f,0.f);
        if (gr >= 0 && gr < 4096) val = *(const float4*)&vb[(size_t)gr*64 + c4];
        *(float4*)&vt[r][c4] = val;
    }
    __syncthreads();
    int dh = t & 63;
    int rr = t >> 6;
#pragma unroll
    for (int q=0;q<16;q++){
        int lr = rr + q*4;
        float acc = attn[((size_t)bh*4096 + row0 + lr)*64 + dh];
#pragma unroll
        for (int s=0;s<33;s++) acc += wk[s]*vt[lr+s][dh];
        attn2[((size_t)b4*4096 + row0 + lr)*512 + h*64 + dh] = acc;
    }
}

// ---------------------------------------------------------------------------
// Host orchestration
// ---------------------------------------------------------------------------
extern "C" void kernel_launch(void* const* d_in, const int* in_sizes, int n_in,
                              void* d_out, int out_size) {
    const float* x      = (const float*)d_in[0];
    const float* norm_w = (const float*)d_in[1];
    const float* norm_b = (const float*)d_in[2];
    const float* Wqkv   = (const float*)d_in[3];
    const float* Wout   = (const float*)d_in[4];
    const float* bout   = (const float*)d_in[5];
    const float* conv_w = (const float*)d_in[6];
    float* out = (float*)d_out;

    float *xn,*q,*k,*v,*ql,*kl,*a2,*z0,*z1,*t1,*t2,*t3,*w,*w2,*attn,*attn2,*red;
    cudaGetSymbolAddress((void**)&xn,   g_xn);
    cudaGetSymbolAddress((void**)&q,    g_q);
    cudaGetSymbolAddress((void**)&k,    g_k);
    cudaGetSymbolAddress((void**)&v,    g_v);
    cudaGetSymbolAddress((void**)&ql,   g_ql);
    cudaGetSymbolAddress((void**)&kl,   g_kl);
    cudaGetSymbolAddress((void**)&a2,   g_a2);
    cudaGetSymbolAddress((void**)&z0,   g_z0);
    cudaGetSymbolAddress((void**)&z1,   g_z1);
    cudaGetSymbolAddress((void**)&t1,   g_t1);
    cudaGetSymbolAddress((void**)&t2,   g_t2);
    cudaGetSymbolAddress((void**)&t3,   g_t3);
    cudaGetSymbolAddress((void**)&w,    g_w);
    cudaGetSymbolAddress((void**)&w2,   g_w2);
    cudaGetSymbolAddress((void**)&attn, g_attn);
    cudaGetSymbolAddress((void**)&attn2,g_attn2);
    cudaGetSymbolAddress((void**)&red,  g_red);

    cudaFuncSetAttribute(flash_kernel, cudaFuncAttributeMaxDynamicSharedMemorySize, SMEM_FLASH);

    // 1. LayerNorm
    ln_kernel<<<16384, 128>>>(x, norm_w, norm_b, xn);
    // 2. QKV projection (tf32 tensor cores, fused scatter + q scale)
    mma_gemm<0,512,1536,512><<<dim3(12,128), 256>>>(
        xn, Wqkv, q, k, v, nullptr, nullptr, 0.f, 0.f);
    // 3. landmarks
    landmark_kernel<<<2048, 256>>>(q, ql);
    landmark_kernel<<<2048, 256>>>(k, kl);
    // 4. a2 = softmax(q_l k_l^T)
    a2_kernel<<<dim3(32,32), 256>>>(ql, kl, a2);
    // 5. pinv init scalars + z0 = a2^T/(col*row)
    red_init_kernel<<<1, 32>>>(red);
    colsum_kernel<<<32, 256>>>(a2, red);
    rowsum_kernel<<<32, 256>>>(a2, red);
    zinit_kernel<<<8192, 256>>>(a2, red, z0);
    // 6. w = softmax(q_l k^T) @ v
    flash_kernel<<<dim3(4,32), 256, SMEM_FLASH>>>(ql, k, v, w, 256, 4096);
    // 7. Newton-Schulz pinv (tf32 tensor cores, fused epilogues)
    float* zin = z0; float* zout = z1;
    for (int it = 0; it < 6; it++) {
        mma_gemm<2,256,256,256><<<dim3(2,2,32), 256>>>(
            a2, zin, t1, nullptr, nullptr, nullptr, nullptr, 0.f, 1.f);
        mma_gemm<2,256,256,256><<<dim3(2,2,32), 256>>>(
            t1, t1, t2, nullptr, nullptr, nullptr, nullptr, 7.f, -1.f);
        mma_gemm<2,256,256,256><<<dim3(2,2,32), 256>>>(
            t1, t2, t3, nullptr, nullptr, nullptr, nullptr, 15.f, -1.f);
        mma_gemm<2,256,256,256><<<dim3(2,2,32), 256>>>(
            zin, t3, zout, nullptr, nullptr, nullptr, nullptr, 3.25f, -0.25f);
        float* tmp = zin; zin = zout; zout = tmp;
    }
    // 8. w2 = pinv(a2) @ w (small, fp32)
    gemm_b_kernel<<<dim3(1,2,32), 256>>>(zin, w, w2, 0.f, 1.f, 64);
    // 9. attn = softmax(q k_l^T) @ w2
    flash_kernel<<<dim3(64,32), 256, SMEM_FLASH>>>(q, kl, w2, attn, 4096, 256);
    // 10. conv residual + layout
    conv_kernel<<<dim3(64,32), 256>>>(attn, v, conv_w, attn2);
    // 11. output projection + bias + input residual (tf32 tensor cores)
    mma_gemm<1,512,512,512><<<dim3(4,128), 256>>>(
        attn2, Wout, out, nullptr, nullptr, bout, x, 0.f, 0.f);
}

// round 4
// speedup vs baseline: 2.1955x; 1.3340x over previous
#include <cuda_runtime.h>
#include <cuda_bf16.h>
#include <cstdint>

// ---------------------------------------------------------------------------
// Problem constants: b=4, n=4096, D=512, H=8, dh=64, M=256, l=16, 6 iters,
// conv k=33, eps=1e-5
// ---------------------------------------------------------------------------
#define NB   (4*4096*512)
#define MM   (32*256*256)
#define MD   (32*256*64)

__device__ float g_xn[NB];
__device__ float g_q[NB];
__device__ float g_k[NB];
__device__ float g_v[NB];
__device__ float g_ql[MD];
__device__ float g_kl[MD];
__device__ float g_a2[MM];
__device__ float g_z0[MM];
__device__ float g_z1[MM];
__device__ float g_t1[MM];
__device__ float g_t2[MM];
__device__ float g_t3[MM];
__device__ float g_w[MD];
__device__ float g_w2[MD];
__device__ float g_attn[NB];
__device__ float g_attn2[NB];
__device__ float g_red[2];

__device__ __forceinline__ float f2tf(float x) {
    uint32_t u;
    asm("cvt.rna.tf32.f32 %0, %1;" : "=r"(u) : "f"(x));
    return __uint_as_float(u);
}

// ---------------------------------------------------------------------------
// LayerNorm
// ---------------------------------------------------------------------------
__global__ void ln_kernel(const float* __restrict__ x, const float* __restrict__ w,
                          const float* __restrict__ bb, float* __restrict__ out) {
    int row = blockIdx.x;
    const float* xr = x + (size_t)row * 512;
    float* orow = out + (size_t)row * 512;
    int t = threadIdx.x;
    float v[4];
    float s = 0.f;
#pragma unroll
    for (int i = 0; i < 4; i++) { v[i] = xr[t + 128*i]; s += v[i]; }
#pragma unroll
    for (int o = 16; o; o >>= 1) s += __shfl_xor_sync(0xffffffffu, s, o);
    __shared__ float red[4];
    if ((t & 31) == 0) red[t >> 5] = s;
    __syncthreads();
    float mean = (red[0]+red[1]+red[2]+red[3]) * (1.f/512.f);
    float vs = 0.f;
#pragma unroll
    for (int i = 0; i < 4; i++) { float d = v[i]-mean; vs += d*d; }
#pragma unroll
    for (int o = 16; o; o >>= 1) vs += __shfl_xor_sync(0xffffffffu, vs, o);
    __syncthreads();
    if ((t & 31) == 0) red[t >> 5] = vs;
    __syncthreads();
    float var = (red[0]+red[1]+red[2]+red[3]) * (1.f/512.f);
    float rstd = rsqrtf(var + 1e-5f);
#pragma unroll
    for (int i = 0; i < 4; i++) {
        int c = t + 128*i;
        orow[c] = (v[i]-mean)*rstd*w[c] + bb[c];
    }
}

// ---------------------------------------------------------------------------
// TF32 tensor-core GEMM. Block 128x128, BK=16, 256 thr (8 warps, warp 64x32).
// ---------------------------------------------------------------------------
template<int EPI, int LDA, int LDB, int KD>
__global__ __launch_bounds__(256, 2) void mma_gemm(
        const float* __restrict__ A, const float* __restrict__ B,
        float* __restrict__ C0, float* __restrict__ C1, float* __restrict__ C2,
        const float* __restrict__ e0, const float* __restrict__ e1,
        float cA, float cAB) {
    __shared__ float Asm[2][128*20];
    __shared__ float Bsm[2][16*136];
    int tid = threadIdx.x;
    int lane = tid & 31, wid = tid >> 5;
    int wm = wid & 1, wn = wid >> 1;
    int g = lane >> 2, t4 = lane & 3;
    int row0 = blockIdx.y * 128, col0 = blockIdx.x * 128;
    const float* Ag = A;
    const float* Bg = B;
    if (EPI == 2) {
        Ag += (size_t)blockIdx.z * 65536;
        Bg += (size_t)blockIdx.z * 65536;
    }
    int arow = tid >> 1, akq = (tid & 1) * 8;
    int bkr = tid >> 4, bnc = (tid & 15) * 8;

    {
        const float* ap = Ag + (size_t)(row0 + arow) * LDA + akq;
        float4 a0 = *(const float4*)ap;
        float4 a1 = *(const float4*)(ap + 4);
        float* as = &Asm[0][arow*20 + akq];
        as[0]=f2tf(a0.x); as[1]=f2tf(a0.y); as[2]=f2tf(a0.z); as[3]=f2tf(a0.w);
        as[4]=f2tf(a1.x); as[5]=f2tf(a1.y); as[6]=f2tf(a1.z); as[7]=f2tf(a1.w);
        const float* bp = Bg + (size_t)bkr * LDB + col0 + bnc;
        float4 b0 = *(const float4*)bp;
        float4 b1 = *(const float4*)(bp + 4);
        float* bs = &Bsm[0][bkr*136 + bnc];
        bs[0]=f2tf(b0.x); bs[1]=f2tf(b0.y); bs[2]=f2tf(b0.z); bs[3]=f2tf(b0.w);
        bs[4]=f2tf(b1.x); bs[5]=f2tf(b1.y); bs[6]=f2tf(b1.z); bs[7]=f2tf(b1.w);
    }
    __syncthreads();

    float c[4][4][4];
#pragma unroll
    for (int i=0;i<4;i++)
#pragma unroll
        for (int j=0;j<4;j++)
#pragma unroll
            for (int h=0;h<4;h++) c[i][j][h]=0.f;

    const int NIT = KD / 16;
    for (int it = 0; it < NIT; it++) {
        int buf = it & 1;
        float4 pa0, pa1, pb0, pb1;
        if (it + 1 < NIT) {
            int k0 = (it + 1) * 16;
            const float* ap = Ag + (size_t)(row0 + arow) * LDA + k0 + akq;
            pa0 = *(const float4*)ap;
            pa1 = *(const float4*)(ap + 4);
            const float* bp = Bg + (size_t)(k0 + bkr) * LDB + col0 + bnc;
            pb0 = *(const float4*)bp;
            pb1 = *(const float4*)(bp + 4);
        }
#pragma unroll
        for (int ks = 0; ks < 16; ks += 8) {
            uint32_t af[4][4], bf[4][2];
#pragma unroll
            for (int i = 0; i < 4; i++) {
                int r0i = (wm*64 + i*16 + g) * 20 + ks + t4;
                int r1i = r0i + 8*20;
                af[i][0] = __float_as_uint(Asm[buf][r0i]);
                af[i][1] = __float_as_uint(Asm[buf][r1i]);
                af[i][2] = __float_as_uint(Asm[buf][r0i + 4]);
                af[i][3] = __float_as_uint(Asm[buf][r1i + 4]);
            }
#pragma unroll
            for (int j = 0; j < 4; j++) {
                int nc2 = wn*32 + j*8 + g;
                bf[j][0] = __float_as_uint(Bsm[buf][(ks + t4)*136 + nc2]);
                bf[j][1] = __float_as_uint(Bsm[buf][(ks + t4 + 4)*136 + nc2]);
            }
#pragma unroll
            for (int i = 0; i < 4; i++)
#pragma unroll
                for (int j = 0; j < 4; j++) {
                    asm volatile(
                        "mma.sync.aligned.m16n8k8.row.col.f32.tf32.tf32.f32 "
                        "{%0,%1,%2,%3}, {%4,%5,%6,%7}, {%8,%9}, {%0,%1,%2,%3};\n"
                        : "+f"(c[i][j][0]), "+f"(c[i][j][1]),
                          "+f"(c[i][j][2]), "+f"(c[i][j][3])
                        : "r"(af[i][0]), "r"(af[i][1]), "r"(af[i][2]), "r"(af[i][3]),
                          "r"(bf[j][0]), "r"(bf[j][1]));
                }
        }
        if (it + 1 < NIT) {
            int nb = buf ^ 1;
            float* as = &Asm[nb][arow*20 + akq];
            as[0]=f2tf(pa0.x); as[1]=f2tf(pa0.y); as[2]=f2tf(pa0.z); as[3]=f2tf(pa0.w);
            as[4]=f2tf(pa1.x); as[5]=f2tf(pa1.y); as[6]=f2tf(pa1.z); as[7]=f2tf(pa1.w);
            float* bs = &Bsm[nb][bkr*136 + bnc];
            bs[0]=f2tf(pb0.x); bs[1]=f2tf(pb0.y); bs[2]=f2tf(pb0.z); bs[3]=f2tf(pb0.w);
            bs[4]=f2tf(pb1.x); bs[5]=f2tf(pb1.y); bs[6]=f2tf(pb1.z); bs[7]=f2tf(pb1.w);
        }
        __syncthreads();
    }

#pragma unroll
    for (int i = 0; i < 4; i++) {
#pragma unroll
        for (int j = 0; j < 4; j++) {
#pragma unroll
            for (int h = 0; h < 2; h++) {
                int r = row0 + wm*64 + i*16 + g + h*8;
                int cc = col0 + wn*32 + j*8 + 2*t4;
                float v0 = c[i][j][h*2+0], v1 = c[i][j][h*2+1];
                if (EPI == 0) {
                    int b4 = r >> 12, nn = r & 4095;
                    int which = cc >> 9, cs = cc & 511;
                    int hh = cs >> 6, dh = cs & 63;
                    size_t di = ((size_t)(b4*8+hh)*4096 + nn)*64 + dh;
                    if (which == 0) {
                        *(float2*)&C0[di] = make_float2(v0*0.125f, v1*0.125f);
                    } else if (which == 1) {
                        *(float2*)&C1[di] = make_float2(v0, v1);
                    } else {
                        *(float2*)&C2[di] = make_float2(v0, v1);
                    }
                } else if (EPI == 1) {
                    size_t di = (size_t)r*512 + cc;
                    float2 bias = *(const float2*)&e0[cc];
                    float2 xr = *(const float2*)&e1[di];
                    *(float2*)&C0[di] = make_float2(v0+bias.x+xr.x, v1+bias.y+xr.y);
                } else {
                    float2 ae = *(const float2*)&Ag[(size_t)r*256 + cc];
                    size_t di = (size_t)blockIdx.z*65536 + (size_t)r*256 + cc;
                    *(float2*)&C0[di] = make_float2(cA*ae.x + cAB*v0,
                                                    cA*ae.y + cAB*v1);
                }
            }
        }
    }
}

// ---------------------------------------------------------------------------
// Landmarks
// ---------------------------------------------------------------------------
__global__ void landmark_kernel(const float* __restrict__ src, float* __restrict__ dst) {
    int idx = blockIdx.x * 256 + threadIdx.x;
    int dh = idx & 63;
    int mi = (idx >> 6) & 255;
    int bh = idx >> 14;
    const float* p = src + ((size_t)bh*4096 + mi*16)*64 + dh;
    float s = 0.f;
#pragma unroll
    for (int j = 0; j < 16; j++) s += p[j*64];
    dst[idx] = s * 0.0625f;
}

// ---------------------------------------------------------------------------
// a2 = softmax(q_l @ k_l^T)
// ---------------------------------------------------------------------------
__global__ __launch_bounds__(256) void a2_kernel(const float* __restrict__ ql,
        const float* __restrict__ kl, float* __restrict__ a2) {
    __shared__ float klt[256][17];
    int bh = blockIdx.y;
    int r = blockIdx.x * 8 + (threadIdx.x >> 5);
    int lane = threadIdx.x & 31;
    const float* qr = ql + ((size_t)bh*256 + r) * 64;
    const float* kb = kl + (size_t)bh*256*64;
    float acc[8];
#pragma unroll
    for (int i=0;i<8;i++) acc[i]=0.f;
    for (int k0 = 0; k0 < 64; k0 += 16) {
        int c = threadIdx.x;
#pragma unroll
        for (int ii=0; ii<4; ii++) {
            float4 kv = *(const float4*)&kb[(size_t)c*64 + k0 + ii*4];
            klt[c][ii*4+0]=kv.x; klt[c][ii*4+1]=kv.y; klt[c][ii*4+2]=kv.z; klt[c][ii*4+3]=kv.w;
        }
        __syncthreads();
#pragma unroll
        for (int kk=0;kk<16;kk++) {
            float qv = qr[k0+kk];
#pragma unroll
            for (int ii=0;ii<8;ii++) acc[ii] += qv * klt[ii*32+lane][kk];
        }
        __syncthreads();
    }
    float m = acc[0];
#pragma unroll
    for (int ii=1;ii<8;ii++) m = fmaxf(m, acc[ii]);
#pragma unroll
    for (int o=16;o;o>>=1) m = fmaxf(m, __shfl_xor_sync(0xffffffffu,m,o));
    float ssum = 0.f;
#pragma unroll
    for (int ii=0;ii<8;ii++){ acc[ii]=__expf(acc[ii]-m); ssum+=acc[ii]; }
#pragma unroll
    for (int o=16;o;o>>=1) ssum += __shfl_xor_sync(0xffffffffu,ssum,o);
    float inv = 1.f/ssum;
    float* orow = a2 + ((size_t)bh*256 + r) * 256;
#pragma unroll
    for (int ii=0;ii<8;ii++) orow[ii*32+lane] = acc[ii]*inv;
}

// ---------------------------------------------------------------------------
// pinv scalar reductions
// ---------------------------------------------------------------------------
__global__ void red_init_kernel(float* g) { if (threadIdx.x < 2) g[threadIdx.x] = 0.f; }

__global__ void colsum_kernel(const float* __restrict__ a2, float* __restrict__ gred) {
    int bh = blockIdx.x; int j = threadIdx.x;
    const float* base = a2 + (size_t)bh*65536;
    float s = 0.f;
    for (int i=0;i<256;i++) s += fabsf(base[(size_t)i*256 + j]);
#pragma unroll
    for (int o=16;o;o>>=1) s = fmaxf(s, __shfl_xor_sync(0xffffffffu,s,o));
    __shared__ float red[8];
    if ((j&31)==0) red[j>>5]=s;
    __syncthreads();
    if (j==0) {
        float m = red[0];
#pragma unroll
        for (int u=1;u<8;u++) m = fmaxf(m, red[u]);
        atomicMax((int*)&gred[1], __float_as_int(m));
    }
}

__global__ void rowsum_kernel(const float* __restrict__ a2, float* __restrict__ gred) {
    int bh = blockIdx.x; int j = threadIdx.x;
    const float* base = a2 + (size_t)bh*65536;
    float s = 0.f;
    for (int i=0;i<256;i++) s += fabsf(base[(size_t)j*256 + i]);
#pragma unroll
    for (int o=16;o;o>>=1) s = fmaxf(s, __shfl_xor_sync(0xffffffffu,s,o));
    __shared__ float red[8];
    if ((j&31)==0) red[j>>5]=s;
    __syncthreads();
    if (j==0) {
        float m = red[0];
#pragma unroll
        for (int u=1;u<8;u++) m = fmaxf(m, red[u]);
        atomicMax((int*)&gred[0], __float_as_int(m));
    }
}

__global__ void zinit_kernel(const float* __restrict__ a2, const float* __restrict__ gred,
                             float* __restrict__ z) {
    int idx = blockIdx.x*256 + threadIdx.x;
    int j = idx & 255, i = (idx>>8) & 255, bh = idx >> 16;
    float inv = 1.f/(gred[0]*gred[1]);
    z[idx] = a2[((size_t)bh*256 + j)*256 + i] * inv;
}

// ---------------------------------------------------------------------------
// fp32 batched GEMM (tiny w2 = pinv @ w, ncols=64)
// ---------------------------------------------------------------------------
__global__ __launch_bounds__(256) void gemm_b_kernel(
        const float* __restrict__ A, const float* __restrict__ B,
        float* __restrict__ C, float cA, float cAB, int ncols) {
    int bh = blockIdx.z;
    int row0 = blockIdx.y * 128;
    int col0 = blockIdx.x * 64;
    const float* Ab = A + (size_t)bh * 65536;
    const float* Bb = B + (size_t)bh * 256 * ncols;
    float* Cb = C + (size_t)bh * 256 * ncols;
    __shared__ float As[16][132];
    __shared__ float Bs[16][64];
    int t = threadIdx.x;
    int tx = t & 15, ty = t >> 4;
    float acc[8][4];
#pragma unroll
    for (int i=0;i<8;i++)
#pragma unroll
        for (int j=0;j<4;j++) acc[i][j]=0.f;
    int alr = t >> 1;
    int alk = (t & 1) * 8;
    int blr = t >> 4;
    int blc = (t & 15) * 4;
    for (int k0 = 0; k0 < 256; k0 += 16) {
#pragma unroll
        for (int ii=0; ii<2; ii++) {
            float4 av = *(const float4*)&Ab[(size_t)(row0+alr)*256 + k0 + alk + ii*4];
            As[alk+ii*4+0][alr]=av.x; As[alk+ii*4+1][alr]=av.y;
            As[alk+ii*4+2][alr]=av.z; As[alk+ii*4+3][alr]=av.w;
        }
        *(float4*)&Bs[blr][blc] = *(const float4*)&Bb[(size_t)(k0+blr)*ncols + col0 + blc];
        __syncthreads();
#pragma unroll
        for (int k=0;k<16;k++) {
            float a[8], b[4];
            *(float4*)&a[0] = *(const float4*)&As[k][ty*8];
            *(float4*)&a[4] = *(const float4*)&As[k][ty*8+4];
            *(float4*)&b[0] = *(const float4*)&Bs[k][tx*4];
#pragma unroll
            for (int i=0;i<8;i++)
#pragma unroll
                for (int j=0;j<4;j++) acc[i][j] += a[i]*b[j];
        }
        __syncthreads();
    }
#pragma unroll
    for (int i=0;i<8;i++) {
        int r = row0 + ty*8 + i;
#pragma unroll
        for (int j=0;j<4;j++) {
            int c = col0 + tx*4 + j;
            float val = cAB * acc[i][j];
            if (cA != 0.f) val += cA * Ab[(size_t)r*256 + c];
            Cb[(size_t)r*ncols + c] = val;
        }
    }
}

// ---------------------------------------------------------------------------
// TF32 tensor-core flash attention: O = softmax(Q @ K^T) @ V
// 64 q-rows per CTA, 64-wide k tiles. 8 warps: wm=wid&1 (32 rows),
// wn=wid>>1 (16 cols). Each warp 2x2 m16n8k8 frags.
// Pitches: Qs/Ks/Ps 68 (banks 4g+t4), Vs 72 (banks 8t4+g) — conflict-free.
// ---------------------------------------------------------------------------
#define QP 68
#define VP 72
// floats: Qs 4352 | Ks 4352 | Ps 4352 | Vs 4608 | rowm 64 | rowl 64 | redm 256 | reds 256
#define OFF_KS   4352
#define OFF_PS   8704
#define OFF_VS   13056
#define OFF_ROWM 17664
#define OFF_ROWL 17728
#define OFF_REDM 17792
#define OFF_REDS 18048
#define SMEM_FLASH_TC ((18304)*4)

__global__ __launch_bounds__(256) void flash_tc_kernel(
        const float* __restrict__ Q, const float* __restrict__ K,
        const float* __restrict__ V, float* __restrict__ O, int nq, int nk) {
    extern __shared__ float sm[];
    float (*Qs)[QP] = (float(*)[QP])sm;
    float (*Ks)[QP] = (float(*)[QP])(sm + OFF_KS);
    float (*Ps)[QP] = (float(*)[QP])(sm + OFF_PS);
    float (*Vs)[VP] = (float(*)[VP])(sm + OFF_VS);
    float* rowm = sm + OFF_ROWM;
    float* rowl = sm + OFF_ROWL;
    float (*redm)[4] = (float(*)[4])(sm + OFF_REDM);
    float (*reds)[4] = (float(*)[4])(sm + OFF_REDS);

    int tid = threadIdx.x;
    int lane = tid & 31, wid = tid >> 5;
    int wm = wid & 1, wn = wid >> 1;
    int g = lane >> 2, t4 = lane & 3;
    int bh = blockIdx.y;
    int q0 = blockIdx.x * 64;
    const float* Qb = Q + ((size_t)bh*nq + q0) * 64;
    const float* Kb = K + (size_t)bh*nk*64;
    const float* Vb = V + (size_t)bh*nk*64;
    float* Ob = O + ((size_t)bh*nq + q0) * 64;

    // load Q (tf32)
    {
        int r = tid >> 2, kc = (tid & 3) * 16;
#pragma unroll
        for (int ii = 0; ii < 4; ii++) {
            float4 qv = *(const float4*)&Qb[(size_t)r*64 + kc + ii*4];
            Qs[r][kc+ii*4+0]=f2tf(qv.x); Qs[r][kc+ii*4+1]=f2tf(qv.y);
            Qs[r][kc+ii*4+2]=f2tf(qv.z); Qs[r][kc+ii*4+3]=f2tf(qv.w);
        }
    }
    if (tid < 64) { rowm[tid] = -1e30f; rowl[tid] = 0.f; }
    float o[2][2][4];
#pragma unroll
    for (int i=0;i<2;i++)
#pragma unroll
        for (int j=0;j<2;j++)
#pragma unroll
            for (int h=0;h<4;h++) o[i][j][h]=0.f;
    __syncthreads();

    for (int c0 = 0; c0 < nk; c0 += 64) {
        // load K, V tiles (tf32)
        {
            int r = tid >> 2, kc = (tid & 3) * 16;
#pragma unroll
            for (int ii = 0; ii < 4; ii++) {
                float4 kv = *(const float4*)&Kb[(size_t)(c0+r)*64 + kc + ii*4];
                Ks[r][kc+ii*4+0]=f2tf(kv.x); Ks[r][kc+ii*4+1]=f2tf(kv.y);
                Ks[r][kc+ii*4+2]=f2tf(kv.z); Ks[r][kc+ii*4+3]=f2tf(kv.w);
                float4 vv = *(const float4*)&Vb[(size_t)(c0+r)*64 + kc + ii*4];
                Vs[r][kc+ii*4+0]=f2tf(vv.x); Vs[r][kc+ii*4+1]=f2tf(vv.y);
                Vs[r][kc+ii*4+2]=f2tf(vv.z); Vs[r][kc+ii*4+3]=f2tf(vv.w);
            }
        }
        __syncthreads();

        // S = Q @ K^T (2x2 frags per warp)
        float s[2][2][4];
#pragma unroll
        for (int i=0;i<2;i++)
#pragma unroll
            for (int j=0;j<2;j++)
#pragma unroll
                for (int h=0;h<4;h++) s[i][j][h]=0.f;
#pragma unroll
        for (int ks = 0; ks < 64; ks += 8) {
            uint32_t af[2][4], bf[2][2];
#pragma unroll
            for (int i = 0; i < 2; i++) {
                int r = wm*32 + i*16 + g;
                af[i][0] = __float_as_uint(Qs[r][ks+t4]);
                af[i][1] = __float_as_uint(Qs[r+8][ks+t4]);
                af[i][2] = __float_as_uint(Qs[r][ks+t4+4]);
                af[i][3] = __float_as_uint(Qs[r+8][ks+t4+4]);
            }
#pragma unroll
            for (int j = 0; j < 2; j++) {
                int cc = wn*16 + j*8 + g;
                bf[j][0] = __float_as_uint(Ks[cc][ks+t4]);
                bf[j][1] = __float_as_uint(Ks[cc][ks+t4+4]);
            }
#pragma unroll
            for (int i = 0; i < 2; i++)
#pragma unroll
                for (int j = 0; j < 2; j++) {
                    asm volatile(
                        "mma.sync.aligned.m16n8k8.row.col.f32.tf32.tf32.f32 "
                        "{%0,%1,%2,%3}, {%4,%5,%6,%7}, {%8,%9}, {%0,%1,%2,%3};\n"
                        : "+f"(s[i][j][0]), "+f"(s[i][j][1]),
                          "+f"(s[i][j][2]), "+f"(s[i][j][3])
                        : "r"(af[i][0]), "r"(af[i][1]), "r"(af[i][2]), "r"(af[i][3]),
                          "r"(bf[j][0]), "r"(bf[j][1]));
                }
        }

        // row max: per-thread over 4 cols, quad-reduce over t4, cross-warp via smem
        float pm[2][2];
#pragma unroll
        for (int i=0;i<2;i++)
#pragma unroll
            for (int h=0;h<2;h++)
                pm[i][h] = fmaxf(fmaxf(s[i][0][2*h], s[i][0][2*h+1]),
                                 fmaxf(s[i][1][2*h], s[i][1][2*h+1]));
#pragma unroll
        for (int off = 1; off <= 2; off <<= 1) {
#pragma unroll
            for (int i=0;i<2;i++)
#pragma unroll
                for (int h=0;h<2;h++)
                    pm[i][h] = fmaxf(pm[i][h], __shfl_xor_sync(0xffffffffu, pm[i][h], off));
        }
        if (t4 == 0) {
#pragma unroll
            for (int i=0;i<2;i++)
#pragma unroll
                for (int h=0;h<2;h++)
                    redm[wm*32 + i*16 + g + h*8][wn] = pm[i][h];
        }
        __syncthreads();

        float mnew[2][2], scale[2][2];
#pragma unroll
        for (int i=0;i<2;i++)
#pragma unroll
            for (int h=0;h<2;h++) {
                int r = wm*32 + i*16 + g + h*8;
                float m = fmaxf(fmaxf(redm[r][0], redm[r][1]),
                                fmaxf(redm[r][2], redm[r][3]));
                float mo = rowm[r];
                mnew[i][h] = fmaxf(mo, m);
                scale[i][h] = __expf(mo - mnew[i][h]);
            }

        // P = exp(S - mnew); stage to smem (tf32); scale O; partial sums
        float psum[2][2] = {{0.f,0.f},{0.f,0.f}};
#pragma unroll
        for (int i=0;i<2;i++)
#pragma unroll
            for (int j=0;j<2;j++)
#pragma unroll
                for (int h=0;h<2;h++) {
                    int r = wm*32 + i*16 + g + h*8;
                    float p0 = __expf(s[i][j][2*h]   - mnew[i][h]);
                    float p1 = __expf(s[i][j][2*h+1] - mnew[i][h]);
                    *(float2*)&Ps[r][wn*16 + j*8 + 2*t4] = make_float2(f2tf(p0), f2tf(p1));
                    psum[i][h] += p0 + p1;
                    o[i][j][2*h]   *= scale[i][h];
                    o[i][j][2*h+1] *= scale[i][h];
                }
#pragma unroll
        for (int off = 1; off <= 2; off <<= 1) {
#pragma unroll
            for (int i=0;i<2;i++)
#pragma unroll
                for (int h=0;h<2;h++)
                    psum[i][h] += __shfl_xor_sync(0xffffffffu, psum[i][h], off);
        }
        if (t4 == 0) {
#pragma unroll
            for (int i=0;i<2;i++)
#pragma unroll
                for (int h=0;h<2;h++)
                    reds[wm*32 + i*16 + g + h*8][wn] = psum[i][h];
        }
        __syncthreads();

        // rowl/rowm update (one writer per row)
        if (wn == 0 && t4 == 0) {
#pragma unroll
            for (int i=0;i<2;i++)
#pragma unroll
                for (int h=0;h<2;h++) {
                    int r = wm*32 + i*16 + g + h*8;
                    float ps = reds[r][0] + reds[r][1] + reds[r][2] + reds[r][3];
                    rowl[r] = rowl[r]*scale[i][h] + ps;
                    rowm[r] = mnew[i][h];
                }
        }

        // O += P @ V
#pragma unroll
        for (int ks = 0; ks < 64; ks += 8) {
            uint32_t af[2][4], bf[2][2];
#pragma unroll
            for (int i = 0; i < 2; i++) {
                int r = wm*32 + i*16 + g;
                af[i][0] = __float_as_uint(Ps[r][ks+t4]);
                af[i][1] = __float_as_uint(Ps[r+8][ks+t4]);
                af[i][2] = __float_as_uint(Ps[r][ks+t4+4]);
                af[i][3] = __float_as_uint(Ps[r+8][ks+t4+4]);
            }
#pragma unroll
            for (int j = 0; j < 2; j++) {
                int cc = wn*16 + j*8 + g;
                bf[j][0] = __float_as_uint(Vs[ks+t4][cc]);
                bf[j][1] = __float_as_uint(Vs[ks+t4+4][cc]);
            }
#pragma unroll
            for (int i = 0; i < 2; i++)
#pragma unroll
                for (int j = 0; j < 2; j++) {
                    asm volatile(
                        "mma.sync.aligned.m16n8k8.row.col.f32.tf32.tf32.f32 "
                        "{%0,%1,%2,%3}, {%4,%5,%6,%7}, {%8,%9}, {%0,%1,%2,%3};\n"
                        : "+f"(o[i][j][0]), "+f"(o[i][j][1]),
                          "+f"(o[i][j][2]), "+f"(o[i][j][3])
                        : "r"(af[i][0]), "r"(af[i][1]), "r"(af[i][2]), "r"(af[i][3]),
                          "r"(bf[j][0]), "r"(bf[j][1]));
                }
        }
        __syncthreads();
    }

    // epilogue: divide by rowl, write out
#pragma unroll
    for (int i=0;i<2;i++)
#pragma unroll
        for (int j=0;j<2;j++)
#pragma unroll
            for (int h=0;h<2;h++) {
                int r = wm*32 + i*16 + g + h*8;
                int cc = wn*16 + j*8 + 2*t4;
                float inv = 1.f / rowl[r];
                *(float2*)&Ob[(size_t)r*64 + cc] =
                    make_float2(o[i][j][2*h]*inv, o[i][j][2*h+1]*inv);
            }
}

// ---------------------------------------------------------------------------
// Depthwise seq-conv residual + layout transform
// ---------------------------------------------------------------------------
__global__ __launch_bounds__(256) void conv_kernel(
        const float* __restrict__ attn, const float* __restrict__ v,
        const float* __restrict__ cw, float* __restrict__ attn2) {
    __shared__ float vt[96][64];
    __shared__ float wk[33];
    int bh = blockIdx.y; int h = bh & 7; int b4 = bh >> 3;
    int row0 = blockIdx.x * 64;
    int t = threadIdx.x;
    if (t < 33) wk[t] = cw[h*33 + t];
    const float* vb = v + (size_t)bh*4096*64;
#pragma unroll
    for (int i=0;i<6;i++){
        int f = t + i*256;
        int r = f >> 4;
        int c4 = (f & 15) * 4;
        int gr = row0 - 16 + r;
        float4 val = make_float4(0.f,0.f,0.f,0.f);
        if (gr >= 0 && gr < 4096) val = *(const float4*)&vb[(size_t)gr*64 + c4];
        *(float4*)&vt[r][c4] = val;
    }
    __syncthreads();
    int dh = t & 63;
    int rr = t >> 6;
#pragma unroll
    for (int q=0;q<16;q++){
        int lr = rr + q*4;
        float acc = attn[((size_t)bh*4096 + row0 + lr)*64 + dh];
#pragma unroll
        for (int s=0;s<33;s++) acc += wk[s]*vt[lr+s][dh];
        attn2[((size_t)b4*4096 + row0 + lr)*512 + h*64 + dh] = acc;
    }
}

// ---------------------------------------------------------------------------
// Host orchestration
// ---------------------------------------------------------------------------
extern "C" void kernel_launch(void* const* d_in, const int* in_sizes, int n_in,
                              void* d_out, int out_size) {
    const float* x      = (const float*)d_in[0];
    const float* norm_w = (const float*)d_in[1];
    const float* norm_b = (const float*)d_in[2];
    const float* Wqkv   = (const float*)d_in[3];
    const float* Wout   = (const float*)d_in[4];
    const float* bout   = (const float*)d_in[5];
    const float* conv_w = (const float*)d_in[6];
    float* out = (float*)d_out;

    float *xn,*q,*k,*v,*ql,*kl,*a2,*z0,*z1,*t1,*t2,*t3,*w,*w2,*attn,*attn2,*red;
    cudaGetSymbolAddress((void**)&xn,   g_xn);
    cudaGetSymbolAddress((void**)&q,    g_q);
    cudaGetSymbolAddress((void**)&k,    g_k);
    cudaGetSymbolAddress((void**)&v,    g_v);
    cudaGetSymbolAddress((void**)&ql,   g_ql);
    cudaGetSymbolAddress((void**)&kl,   g_kl);
    cudaGetSymbolAddress((void**)&a2,   g_a2);
    cudaGetSymbolAddress((void**)&z0,   g_z0);
    cudaGetSymbolAddress((void**)&z1,   g_z1);
    cudaGetSymbolAddress((void**)&t1,   g_t1);
    cudaGetSymbolAddress((void**)&t2,   g_t2);
    cudaGetSymbolAddress((void**)&t3,   g_t3);
    cudaGetSymbolAddress((void**)&w,    g_w);
    cudaGetSymbolAddress((void**)&w2,   g_w2);
    cudaGetSymbolAddress((void**)&attn, g_attn);
    cudaGetSymbolAddress((void**)&attn2,g_attn2);
    cudaGetSymbolAddress((void**)&red,  g_red);

    cudaFuncSetAttribute(flash_tc_kernel, cudaFuncAttributeMaxDynamicSharedMemorySize, SMEM_FLASH_TC);

    // 1. LayerNorm
    ln_kernel<<<16384, 128>>>(x, norm_w, norm_b, xn);
    // 2. QKV projection (tf32 tensor cores, fused scatter + q scale)
    mma_gemm<0,512,1536,512><<<dim3(12,128), 256>>>(
        xn, Wqkv, q, k, v, nullptr, nullptr, 0.f, 0.f);
    // 3. landmarks
    landmark_kernel<<<2048, 256>>>(q, ql);
    landmark_kernel<<<2048, 256>>>(k, kl);
    // 4. a2 = softmax(q_l k_l^T)
    a2_kernel<<<dim3(32,32), 256>>>(ql, kl, a2);
    // 5. pinv init scalars + z0 = a2^T/(col*row)
    red_init_kernel<<<1, 32>>>(red);
    colsum_kernel<<<32, 256>>>(a2, red);
    rowsum_kernel<<<32, 256>>>(a2, red);
    zinit_kernel<<<8192, 256>>>(a2, red, z0);
    // 6. w = softmax(q_l k^T) @ v (tf32 flash)
    flash_tc_kernel<<<dim3(4,32), 256, SMEM_FLASH_TC>>>(ql, k, v, w, 256, 4096);
    // 7. Newton-Schulz pinv (tf32 tensor cores, fused epilogues)
    float* zin = z0; float* zout = z1;
    for (int it = 0; it < 6; it++) {
        mma_gemm<2,256,256,256><<<dim3(2,2,32), 256>>>(
            a2, zin, t1, nullptr, nullptr, nullptr, nullptr, 0.f, 1.f);
        mma_gemm<2,256,256,256><<<dim3(2,2,32), 256>>>(
            t1, t1, t2, nullptr, nullptr, nullptr, nullptr, 7.f, -1.f);
        mma_gemm<2,256,256,256><<<dim3(2,2,32), 256>>>(
            t1, t2, t3, nullptr, nullptr, nullptr, nullptr, 15.f, -1.f);
        mma_gemm<2,256,256,256><<<dim3(2,2,32), 256>>>(
            zin, t3, zout, nullptr, nullptr, nullptr, nullptr, 3.25f, -0.25f);
        float* tmp = zin; zin = zout; zout = tmp;
    }
    // 8. w2 = pinv(a2) @ w (small, fp32)
    gemm_b_kernel<<<dim3(1,2,32), 256>>>(zin, w, w2, 0.f, 1.f, 64);
    // 9. attn = softmax(q k_l^T) @ w2 (tf32 flash)
    flash_tc_kernel<<<dim3(64,32), 256, SMEM_FLASH_TC>>>(q, kl, w2, attn, 4096, 256);
    // 10. conv residual + layout
    conv_kernel<<<dim3(64,32), 256>>>(attn, v, conv_w, attn2);
    // 11. output projection + bias + input residual (tf32 tensor cores)
    mma_gemm<1,512,512,512><<<dim3(4,128), 256>>>(
        attn2, Wout, out, nullptr, nullptr, bout, x, 0.f, 0.f);
}